// round 11
// baseline (speedup 1.0000x reference)
#include <cuda_runtime.h>
#include <cstdint>

// Problem constants (fixed by the reference):
//   x    : [B=8, N=50000, C=128] f32
//   cols : [M=25000, K=3] int32
//   vals : [M=25000, K=3] f32
//   out  : [B=8, M=25000, C=128] f32
// out[b,m,c] = sum_k vals[m,k] * x[b, cols[m,k], c]
//
// Final-form config: batch-major grid (blockIdx.y = b) keeps the 25.6MB
// per-batch x slice L2-hot; ONE m per warp with grid.x = 3125 dividing
// M = 25000 exactly -> completely branch-free kernel (no loop, no tail,
// no bounds check), 3 front-batched gather LDG.128, minimal registers,
// 100% theoretical occupancy. Plain coherent stores (best of R6 A/B).

#define B_DIM 8
#define N_DIM 50000
#define C_DIM 128
#define M_DIM 25000
#define K_DIM 3
#define WARPS_PER_BLOCK 8

__global__ __launch_bounds__(256, 8)
void mesh_sampling_kernel(const float* __restrict__ x,
                          const int*   __restrict__ cols,
                          const float* __restrict__ vals,
                          float*       __restrict__ out)
{
    const int b    = blockIdx.y;
    const int warp = threadIdx.x >> 5;
    const int lane = threadIdx.x & 31;   // owns channels [4*lane, 4*lane+4)

    // Exact coverage: 3125 blocks * 8 warps = 25000 m's. No bounds check.
    const int m = blockIdx.x * WARPS_PER_BLOCK + warp;

    const float* __restrict__ xb   = x   + (size_t)b * ((size_t)N_DIM * C_DIM);
    float*       __restrict__ outb = out + (size_t)b * ((size_t)M_DIM * C_DIM);

    // Uniform (warp-broadcast) loads of indices & weights.
    const int   c0 = __ldg(cols + (size_t)m * K_DIM + 0);
    const int   c1 = __ldg(cols + (size_t)m * K_DIM + 1);
    const int   c2 = __ldg(cols + (size_t)m * K_DIM + 2);
    const float v0 = __ldg(vals + (size_t)m * K_DIM + 0);
    const float v1 = __ldg(vals + (size_t)m * K_DIM + 1);
    const float v2 = __ldg(vals + (size_t)m * K_DIM + 2);

    // Three independent gathers, front-batched (no intervening branches).
    const float4 a = __ldg((const float4*)(xb + (size_t)c0 * C_DIM) + lane);
    const float4 g = __ldg((const float4*)(xb + (size_t)c1 * C_DIM) + lane);
    const float4 c = __ldg((const float4*)(xb + (size_t)c2 * C_DIM) + lane);

    float4 r;
    r.x = v0 * a.x + v1 * g.x + v2 * c.x;
    r.y = v0 * a.y + v1 * g.y + v2 * c.y;
    r.z = v0 * a.z + v1 * g.z + v2 * c.z;
    r.w = v0 * a.w + v1 * g.w + v2 * c.w;

    *((float4*)(outb + (size_t)m * C_DIM) + lane) = r;
}

extern "C" void kernel_launch(void* const* d_in, const int* in_sizes, int n_in,
                              void* d_out, int out_size)
{
    const float* x    = (const float*)d_in[0];
    const int*   cols = (const int*)  d_in[1];
    const float* vals = (const float*)d_in[2];
    float*       out  = (float*)      d_out;

    dim3 grid(M_DIM / WARPS_PER_BLOCK, B_DIM);   // (3125, 8), exact
    mesh_sampling_kernel<<<grid, 256>>>(x, cols, vals, out);
}

// round 13
// speedup vs baseline: 1.0085x; 1.0085x over previous
#include <cuda_runtime.h>
#include <cstdint>

// Problem constants (fixed by the reference):
//   x    : [B=8, N=50000, C=128] f32
//   cols : [M=25000, K=3] int32
//   vals : [M=25000, K=3] f32
//   out  : [B=8, M=25000, C=128] f32
// out[b,m,c] = sum_k vals[m,k] * x[b, cols[m,k], c]
//
// Batch-major grid (blockIdx.y = b): per-batch 25.6MB x slice stays L2-hot.
// Block = 320 threads (10 warps), each warp does 2 m's:
//   10 * 2 * 1250 = 25000 exactly -> ENTIRELY branch-free,
//   all 6 gather LDG.128 front-batched (MLP_p1 = 6),
//   launch_bounds(320,5) -> 50 warps/SM at 40 regs (no spill).
// Plain coherent stores (best of the R6 store-policy A/B).

#define B_DIM 8
#define N_DIM 50000
#define C_DIM 128
#define M_DIM 25000
#define K_DIM 3
#define WARPS_PER_BLOCK 10
#define MS_PER_WARP 2

__global__ __launch_bounds__(320, 5)
void mesh_sampling_kernel(const float* __restrict__ x,
                          const int*   __restrict__ cols,
                          const float* __restrict__ vals,
                          float*       __restrict__ out)
{
    const int b    = blockIdx.y;
    const int warp = threadIdx.x >> 5;
    const int lane = threadIdx.x & 31;   // owns channels [4*lane, 4*lane+4)

    // Exact coverage: (blockIdx.x * 10 + warp) in [0, 12500) -> m0 in [0, 25000)
    const int m0 = (blockIdx.x * WARPS_PER_BLOCK + warp) * MS_PER_WARP;

    const float* __restrict__ xb   = x   + (size_t)b * ((size_t)N_DIM * C_DIM);
    float*       __restrict__ outb = out + (size_t)b * ((size_t)M_DIM * C_DIM);

    // Uniform (warp-broadcast) loads of indices & weights for both m's.
    const int   c00 = __ldg(cols + (size_t)m0 * K_DIM + 0);
    const int   c01 = __ldg(cols + (size_t)m0 * K_DIM + 1);
    const int   c02 = __ldg(cols + (size_t)m0 * K_DIM + 2);
    const int   c10 = __ldg(cols + (size_t)m0 * K_DIM + 3);
    const int   c11 = __ldg(cols + (size_t)m0 * K_DIM + 4);
    const int   c12 = __ldg(cols + (size_t)m0 * K_DIM + 5);
    const float v00 = __ldg(vals + (size_t)m0 * K_DIM + 0);
    const float v01 = __ldg(vals + (size_t)m0 * K_DIM + 1);
    const float v02 = __ldg(vals + (size_t)m0 * K_DIM + 2);
    const float v10 = __ldg(vals + (size_t)m0 * K_DIM + 3);
    const float v11 = __ldg(vals + (size_t)m0 * K_DIM + 4);
    const float v12 = __ldg(vals + (size_t)m0 * K_DIM + 5);

    // Six independent gathers, front-batched (no branches anywhere).
    const float4 a0 = __ldg((const float4*)(xb + (size_t)c00 * C_DIM) + lane);
    const float4 b0 = __ldg((const float4*)(xb + (size_t)c01 * C_DIM) + lane);
    const float4 d0 = __ldg((const float4*)(xb + (size_t)c02 * C_DIM) + lane);
    const float4 a1 = __ldg((const float4*)(xb + (size_t)c10 * C_DIM) + lane);
    const float4 b1 = __ldg((const float4*)(xb + (size_t)c11 * C_DIM) + lane);
    const float4 d1 = __ldg((const float4*)(xb + (size_t)c12 * C_DIM) + lane);

    float4 r0;
    r0.x = v00 * a0.x + v01 * b0.x + v02 * d0.x;
    r0.y = v00 * a0.y + v01 * b0.y + v02 * d0.y;
    r0.z = v00 * a0.z + v01 * b0.z + v02 * d0.z;
    r0.w = v00 * a0.w + v01 * b0.w + v02 * d0.w;
    *((float4*)(outb + (size_t)m0 * C_DIM) + lane) = r0;

    float4 r1;
    r1.x = v10 * a1.x + v11 * b1.x + v12 * d1.x;
    r1.y = v10 * a1.y + v11 * b1.y + v12 * d1.y;
    r1.z = v10 * a1.z + v11 * b1.z + v12 * d1.z;
    r1.w = v10 * a1.w + v11 * b1.w + v12 * d1.w;
    *((float4*)(outb + (size_t)(m0 + 1) * C_DIM) + lane) = r1;
}

extern "C" void kernel_launch(void* const* d_in, const int* in_sizes, int n_in,
                              void* d_out, int out_size)
{
    const float* x    = (const float*)d_in[0];
    const int*   cols = (const int*)  d_in[1];
    const float* vals = (const float*)d_in[2];
    float*       out  = (float*)      d_out;

    // 1250 * 10 warps * 2 m = 25000 exactly.
    dim3 grid(M_DIM / (WARPS_PER_BLOCK * MS_PER_WARP), B_DIM);   // (1250, 8)
    mesh_sampling_kernel<<<grid, 320>>>(x, cols, vals, out);
}

// round 14
// speedup vs baseline: 1.0471x; 1.0383x over previous
#include <cuda_runtime.h>
#include <cstdint>

// Problem constants (fixed by the reference):
//   x    : [B=8, N=50000, C=128] f32
//   cols : [M=25000, K=3] int32
//   vals : [M=25000, K=3] f32
//   out  : [B=8, M=25000, C=128] f32
// out[b,m,c] = sum_k vals[m,k] * x[b, cols[m,k], c]
//
// FINAL KERNEL (best measured config across 13 rounds):
//  * Batch-major grid (blockIdx.y = b): the chip sweeps one batch at a time,
//    keeping that batch's 25.6MB x slice L2-resident so duplicate col draws
//    (75k draws over ~38.8k unique rows/batch) hit L2 instead of DRAM.
//    This was the single change that actually moved the needle (53.2 -> 43.5us).
//  * One warp per (b, m-pair): lane owns a float4 of channels -> each gather
//    is a fully-coalesced warp-wide 512B read (LDG.128).
//  * Plain coherent stores (beat __stcs by ~2pts DRAM efficiency in A/B).
//  * 32 regs, ~78% achieved occupancy.
// Measured: ncu 39.9us, DRAM 72.9% active, ~230MB total traffic (~= compulsory
// floor). Sweeps of MLP (3..15), occupancy (20..80%), store policy, and L2
// cache hints all landed within noise of this point -> this is the
// random-gather + stream-write DRAM-efficiency roofline for this problem.

#define B_DIM 8
#define N_DIM 50000
#define C_DIM 128
#define M_DIM 25000
#define K_DIM 3
#define MS_PER_WARP 2
#define WARPS_PER_BLOCK 8

__global__ __launch_bounds__(256, 8)
void mesh_sampling_kernel(const float* __restrict__ x,
                          const int*   __restrict__ cols,
                          const float* __restrict__ vals,
                          float*       __restrict__ out)
{
    const int b    = blockIdx.y;
    const int warp = threadIdx.x >> 5;
    const int lane = threadIdx.x & 31;   // owns channels [4*lane, 4*lane+4)

    const int m0 = (blockIdx.x * WARPS_PER_BLOCK + warp) * MS_PER_WARP;

    const float* __restrict__ xb   = x   + (size_t)b * ((size_t)N_DIM * C_DIM);
    float*       __restrict__ outb = out + (size_t)b * ((size_t)M_DIM * C_DIM);

#pragma unroll
    for (int mi = 0; mi < MS_PER_WARP; ++mi) {
        const int m = m0 + mi;
        if (m >= M_DIM) break;

        // Uniform (warp-broadcast) loads of indices & weights
        const int   c0 = __ldg(cols + (size_t)m * K_DIM + 0);
        const int   c1 = __ldg(cols + (size_t)m * K_DIM + 1);
        const int   c2 = __ldg(cols + (size_t)m * K_DIM + 2);
        const float v0 = __ldg(vals + (size_t)m * K_DIM + 0);
        const float v1 = __ldg(vals + (size_t)m * K_DIM + 1);
        const float v2 = __ldg(vals + (size_t)m * K_DIM + 2);

        const float4 a = __ldg((const float4*)(xb + (size_t)c0 * C_DIM) + lane);
        const float4 bb= __ldg((const float4*)(xb + (size_t)c1 * C_DIM) + lane);
        const float4 c = __ldg((const float4*)(xb + (size_t)c2 * C_DIM) + lane);

        float4 r;
        r.x = v0 * a.x + v1 * bb.x + v2 * c.x;
        r.y = v0 * a.y + v1 * bb.y + v2 * c.y;
        r.z = v0 * a.z + v1 * bb.z + v2 * c.z;
        r.w = v0 * a.w + v1 * bb.w + v2 * c.w;

        *((float4*)(outb + (size_t)m * C_DIM) + lane) = r;
    }
}

extern "C" void kernel_launch(void* const* d_in, const int* in_sizes, int n_in,
                              void* d_out, int out_size)
{
    const float* x    = (const float*)d_in[0];
    const int*   cols = (const int*)  d_in[1];
    const float* vals = (const float*)d_in[2];
    float*       out  = (float*)      d_out;

    const int ms_per_block = WARPS_PER_BLOCK * MS_PER_WARP;          // 16
    dim3 grid((M_DIM + ms_per_block - 1) / ms_per_block, B_DIM);     // (1563, 8)
    mesh_sampling_kernel<<<grid, 256>>>(x, cols, vals, out);
}